// round 1
// baseline (speedup 1.0000x reference)
#include <cuda_runtime.h>
#include <cuda_bf16.h>
#include <math.h>

// Problem constants (fixed by setup_inputs: N_VERT=2048, NF=8, order=16, LMAX=2)
constexpr int N = 2048;
constexpr int NF = 8;
constexpr int ORDER = 16;
constexpr int NCOEF = ORDER + 1;         // 17
constexpr size_t NN = (size_t)N * N;     // 4M elements = 16MB per slab

// Scratch: all Chebyshev matrices T_0..T_16 (T_0 = I stored explicitly),
// plus F = 2(L - I). __device__ globals = sanctioned scratch (no cudaMalloc).
__device__ float g_Ts[(size_t)NCOEF * NN];   // 272 MB
__device__ float g_F[NN];                    // 16 MB
__device__ float g_cw[NCOEF * NF];           // weighted coeffs (cw[0] already *0.5)

// ---------------------------------------------------------------------------
// Packed fp32x2 helpers (Blackwell sm_100+): 2x FFMA throughput vs scalar FFMA
// ---------------------------------------------------------------------------
__device__ __forceinline__ unsigned long long ffma2(unsigned long long a,
                                                    unsigned long long b,
                                                    unsigned long long c) {
    unsigned long long d;
    asm("fma.rn.f32x2 %0, %1, %2, %3;" : "=l"(d) : "l"(a), "l"(b), "l"(c));
    return d;
}
__device__ __forceinline__ unsigned long long pack2(float x) {
    unsigned long long d;
    unsigned int u = __float_as_uint(x);
    asm("mov.b64 %0, {%1, %1};" : "=l"(d) : "r"(u));
    return d;
}

// ---------------------------------------------------------------------------
// Coefficient kernel: cw[k][f] = (2/17) * sum_n cos(pi k (n+.5)/17) *
//                                 exp(-(cos(pi(n+.5)/17)+1) * tau_f)
// with cw[0][f] additionally scaled by 0.5 (the T0 term in cheby_op).
// ---------------------------------------------------------------------------
__global__ void cheb_coeff(const float* __restrict__ taus, float* __restrict__ cw) {
    int t = threadIdx.x;
    if (t < NCOEF * NF) {
        int k = t >> 3, f = t & 7;
        double tau = (double)taus[f];
        const double PI = 3.14159265358979323846;
        double s = 0.0;
        for (int n = 0; n < NCOEF; n++) {
            double arg = (n + 0.5) / (double)NCOEF;
            double pt = cos(PI * arg) + 1.0;          // a1*cos + a2, a1=a2=1
            s += cos(PI * (double)k * arg) * exp(-pt * tau);
        }
        double v = (2.0 / (double)NCOEF) * s;
        if (k == 0) v *= 0.5;
        cw[t] = (float)v;
    }
}

// ---------------------------------------------------------------------------
// Prep: T0 = I, T1 = L - I, F = 2(L - I). One thread per float4.
// ---------------------------------------------------------------------------
__global__ void __launch_bounds__(256)
cheb_prep(const float* __restrict__ L, float* __restrict__ F,
          float* __restrict__ T0, float* __restrict__ T1) {
    size_t idx = (size_t)blockIdx.x * 256 + threadIdx.x;   // float4 index
    int i = (int)(idx >> 9);            // N/4 = 512 float4 per row
    int j = ((int)(idx & 511)) << 2;
    size_t off = (size_t)i * N + j;
    float4 l = *(const float4*)(L + off);
    float m[4] = {l.x, l.y, l.z, l.w};
    float t0[4] = {0.f, 0.f, 0.f, 0.f};
#pragma unroll
    for (int c = 0; c < 4; c++) {
        if (j + c == i) { m[c] -= 1.0f; t0[c] = 1.0f; }
    }
    *(float4*)(T0 + off) = make_float4(t0[0], t0[1], t0[2], t0[3]);
    *(float4*)(T1 + off) = make_float4(m[0], m[1], m[2], m[3]);
    *(float4*)(F + off)  = make_float4(2.f*m[0], 2.f*m[1], 2.f*m[2], 2.f*m[3]);
}

// ---------------------------------------------------------------------------
// GEMM: Cout = A @ B - Cold   (A = F = 2(L-I), so this is the Cheb step)
// 128x128 block tile, BK=16, 256 threads, 8x8 microtile as 8x4 f32x2 pairs.
// Double-buffered smem; A stored transposed with stride 136 (conflict-free).
// ---------------------------------------------------------------------------
__global__ void __launch_bounds__(256, 2)
cheb_gemm(const float* __restrict__ A, const float* __restrict__ B,
          const float* __restrict__ Cold, float* __restrict__ Cout) {
    __shared__ float As[2][16][136];   // [k][row], padded: conflict-free T-store
    __shared__ float Bs[2][16][128];   // [k][col]

    const int tid = threadIdx.x;
    const int bx = blockIdx.x, by = blockIdx.y;
    const int tx8 = (tid & 15) << 3;
    const int ty8 = (tid >> 4) << 3;

    // global->smem load mapping
    const int aRow = tid >> 2;           // 0..63 (two rows: +0, +64)
    const int aCol = (tid & 3) << 2;     // 0,4,8,12
    const int bRow = tid >> 5;           // 0..7  (two rows: +0, +8)
    const int bCol = (tid & 31) << 2;    // 0..124

    const float* Ab = A + (size_t)(by * 128) * N;
    const float* Bb = B + bx * 128;

    float4 aR[2], bR[2];
#pragma unroll
    for (int r = 0; r < 2; r++) {
        aR[r] = *(const float4*)(Ab + (size_t)(aRow + r * 64) * N + aCol);
        bR[r] = *(const float4*)(Bb + (size_t)(bRow + r * 8) * N + bCol);
    }
#pragma unroll
    for (int r = 0; r < 2; r++) {
        As[0][aCol + 0][aRow + r * 64] = aR[r].x;
        As[0][aCol + 1][aRow + r * 64] = aR[r].y;
        As[0][aCol + 2][aRow + r * 64] = aR[r].z;
        As[0][aCol + 3][aRow + r * 64] = aR[r].w;
        *(float4*)&Bs[0][bRow + r * 8][bCol] = bR[r];
    }
    __syncthreads();

    unsigned long long acc[8][4];
#pragma unroll
    for (int i = 0; i < 8; i++)
#pragma unroll
        for (int j = 0; j < 4; j++) acc[i][j] = 0ull;

    constexpr int NT = N / 16;   // 128 k-tiles
    int buf = 0;
    for (int t = 0; t < NT; t++) {
        const int k0 = (t + 1) * 16;
        if (t < NT - 1) {
#pragma unroll
            for (int r = 0; r < 2; r++) {
                aR[r] = *(const float4*)(Ab + (size_t)(aRow + r * 64) * N + k0 + aCol);
                bR[r] = *(const float4*)(Bb + (size_t)(k0 + bRow + r * 8) * N + bCol);
            }
        }
#pragma unroll
        for (int kk = 0; kk < 16; kk++) {
            const float4 a0 = *(const float4*)&As[buf][kk][ty8];
            const float4 a1 = *(const float4*)&As[buf][kk][ty8 + 4];
            const ulonglong2 bq0 = *(const ulonglong2*)&Bs[buf][kk][tx8];
            const ulonglong2 bq1 = *(const ulonglong2*)&Bs[buf][kk][tx8 + 4];
            const unsigned long long bp0 = bq0.x, bp1 = bq0.y, bp2 = bq1.x, bp3 = bq1.y;
            const float av[8] = {a0.x, a0.y, a0.z, a0.w, a1.x, a1.y, a1.z, a1.w};
#pragma unroll
            for (int i = 0; i < 8; i++) {
                const unsigned long long ap = pack2(av[i]);
                acc[i][0] = ffma2(ap, bp0, acc[i][0]);
                acc[i][1] = ffma2(ap, bp1, acc[i][1]);
                acc[i][2] = ffma2(ap, bp2, acc[i][2]);
                acc[i][3] = ffma2(ap, bp3, acc[i][3]);
            }
        }
        if (t < NT - 1) {
            const int nb = buf ^ 1;
#pragma unroll
            for (int r = 0; r < 2; r++) {
                As[nb][aCol + 0][aRow + r * 64] = aR[r].x;
                As[nb][aCol + 1][aRow + r * 64] = aR[r].y;
                As[nb][aCol + 2][aRow + r * 64] = aR[r].z;
                As[nb][aCol + 3][aRow + r * 64] = aR[r].w;
                *(float4*)&Bs[nb][bRow + r * 8][bCol] = bR[r];
            }
        }
        __syncthreads();
        buf ^= 1;
    }

    // Epilogue: Cout = acc - Cold  (factor 2 is pre-folded into A=F)
    const float* accf = reinterpret_cast<const float*>(acc);
    const int row0 = by * 128 + ty8;
    const int col0 = bx * 128 + tx8;
#pragma unroll
    for (int i = 0; i < 8; i++) {
        const float* af = accf + i * 8;
        const size_t off = (size_t)(row0 + i) * N + col0;
        const float4 c0 = *(const float4*)(Cold + off);
        const float4 c1 = *(const float4*)(Cold + off + 4);
        *(float4*)(Cout + off)     = make_float4(af[0] - c0.x, af[1] - c0.y,
                                                 af[2] - c0.z, af[3] - c0.w);
        *(float4*)(Cout + off + 4) = make_float4(af[4] - c1.x, af[5] - c1.y,
                                                 af[6] - c1.z, af[7] - c1.w);
    }
}

// ---------------------------------------------------------------------------
// Finalize: out[f*N+i][j] = sum_{k=0..16} cw[k][f] * T_k[i][j]
// One thread per float4. T_k reads shared across all 8 filters (8x reuse).
// ---------------------------------------------------------------------------
__global__ void __launch_bounds__(256)
cheb_finalize(const float* __restrict__ Ts, const float* __restrict__ cw,
              float* __restrict__ out) {
    __shared__ float cws[NCOEF * NF];
    if (threadIdx.x < NCOEF * NF) cws[threadIdx.x] = cw[threadIdx.x];
    __syncthreads();

    size_t idx = (size_t)blockIdx.x * 256 + threadIdx.x;
    int i = (int)(idx >> 9);
    int j = ((int)(idx & 511)) << 2;
    size_t off = (size_t)i * N + j;

    float4 t[NCOEF];
#pragma unroll
    for (int k = 0; k < NCOEF; k++)
        t[k] = *(const float4*)(Ts + (size_t)k * NN + off);

#pragma unroll
    for (int f = 0; f < NF; f++) {
        float4 s = make_float4(0.f, 0.f, 0.f, 0.f);
#pragma unroll
        for (int k = 0; k < NCOEF; k++) {
            float c = cws[k * NF + f];
            s.x += c * t[k].x; s.y += c * t[k].y;
            s.z += c * t[k].z; s.w += c * t[k].w;
        }
        *(float4*)(out + (size_t)f * NN + off) = s;
    }
}

// ---------------------------------------------------------------------------
// Launch: graph-capturable, allocation-free.
// ---------------------------------------------------------------------------
extern "C" void kernel_launch(void* const* d_in, const int* in_sizes, int n_in,
                              void* d_out, int out_size) {
    const float* L    = (const float*)d_in[0];
    const float* taus = (const float*)d_in[1];
    float* out = (float*)d_out;

    float *Ts, *F, *cw;
    cudaGetSymbolAddress((void**)&Ts, g_Ts);
    cudaGetSymbolAddress((void**)&F, g_F);
    cudaGetSymbolAddress((void**)&cw, g_cw);

    cheb_coeff<<<1, 160>>>(taus, cw);
    cheb_prep<<<(int)(NN / 4 / 256), 256>>>(L, F, Ts, Ts + NN);

    dim3 grid(N / 128, N / 128), block(256);
    for (int k = 2; k <= ORDER; k++) {
        cheb_gemm<<<grid, block>>>(F,
                                   Ts + (size_t)(k - 1) * NN,   // T_{k-1}
                                   Ts + (size_t)(k - 2) * NN,   // T_{k-2}
                                   Ts + (size_t)k * NN);        // T_k
    }
    cheb_finalize<<<(int)(NN / 4 / 256), 256>>>(Ts, cw, out);
}

// round 3
// speedup vs baseline: 2.1182x; 2.1182x over previous
#include <cuda_runtime.h>
#include <cuda_bf16.h>
#include <math.h>
#include <cstdint>

// Problem constants (fixed): N=2048, NF=8, order=16, LMAX=2 => a1=a2=1
constexpr int N = 2048;
constexpr int NF = 8;
constexpr int ORDER = 16;
constexpr int NCOEF = ORDER + 1;          // 17
constexpr size_t NN = (size_t)N * N;      // 4M elems

// Scratch (__device__ globals = sanctioned, no cudaMalloc)
__device__ float         g_Ts[(size_t)NCOEF * NN];   // T_0..T_16 fp32 (272MB)
__device__ __nv_bfloat16 g_hi[(size_t)NCOEF * NN];   // bf16 hi of T_k
__device__ __nv_bfloat16 g_lo[(size_t)NCOEF * NN];   // bf16 lo of T_k
__device__ __nv_bfloat16 g_Fhi[NN];                  // F = 2(L-I) split
__device__ __nv_bfloat16 g_Flo[NN];
__device__ float         g_cw[NCOEF * NF];

// ---------------------------------------------------------------------------
// PTX helpers (arch-neutral: sm_80+ features only; harness targets sm_100 base)
// ---------------------------------------------------------------------------
__device__ __forceinline__ uint32_t smem_u32(const void* p) {
    uint32_t a;
    asm("{ .reg .u64 t; cvta.to.shared.u64 t, %1; cvt.u32.u64 %0, t; }" : "=r"(a) : "l"(p));
    return a;
}
__device__ __forceinline__ void cp16(uint32_t dst, const void* src) {
    asm volatile("cp.async.cg.shared.global [%0], [%1], 16;" :: "r"(dst), "l"(src));
}
#define CP_COMMIT() asm volatile("cp.async.commit_group;" ::: "memory")

__device__ __forceinline__ void ldsm4(uint32_t (&r)[4], uint32_t addr) {
    asm volatile("ldmatrix.sync.aligned.m8n8.x4.shared.b16 {%0,%1,%2,%3}, [%4];"
                 : "=r"(r[0]), "=r"(r[1]), "=r"(r[2]), "=r"(r[3]) : "r"(addr));
}
__device__ __forceinline__ void mma_bf16(float (&d)[4], const uint32_t (&a)[4],
                                         uint32_t b0, uint32_t b1) {
    asm volatile("mma.sync.aligned.m16n8k16.row.col.f32.bf16.bf16.f32 "
                 "{%0,%1,%2,%3},{%4,%5,%6,%7},{%8,%9},{%0,%1,%2,%3};"
                 : "+f"(d[0]), "+f"(d[1]), "+f"(d[2]), "+f"(d[3])
                 : "r"(a[0]), "r"(a[1]), "r"(a[2]), "r"(a[3]), "r"(b0), "r"(b1));
}

// ---------------------------------------------------------------------------
// Chebyshev coefficients (cw[0] pre-scaled by 0.5)
// ---------------------------------------------------------------------------
__global__ void cheb_coeff(const float* __restrict__ taus, float* __restrict__ cw) {
    int t = threadIdx.x;
    if (t < NCOEF * NF) {
        int k = t >> 3, f = t & 7;
        double tau = (double)taus[f];
        const double PI = 3.14159265358979323846;
        double s = 0.0;
        for (int n = 0; n < NCOEF; n++) {
            double arg = (n + 0.5) / (double)NCOEF;
            s += cos(PI * (double)k * arg) * exp(-(cos(PI * arg) + 1.0) * tau);
        }
        double v = (2.0 / (double)NCOEF) * s;
        if (k == 0) v *= 0.5;
        cw[t] = (float)v;
    }
}

// ---------------------------------------------------------------------------
// Prep: T0=I, T1=L-I (+bf16 split), F=2(L-I) as bf16 split
// ---------------------------------------------------------------------------
__device__ __forceinline__ void split_store(float x, __nv_bfloat16* hi, __nv_bfloat16* lo) {
    __nv_bfloat16 h = __float2bfloat16(x);
    *hi = h;
    *lo = __float2bfloat16(x - __bfloat162float(h));
}

__global__ void __launch_bounds__(256)
cheb_prep(const float* __restrict__ L, float* __restrict__ T0, float* __restrict__ T1,
          __nv_bfloat16* __restrict__ T1hi, __nv_bfloat16* __restrict__ T1lo,
          __nv_bfloat16* __restrict__ Fhi, __nv_bfloat16* __restrict__ Flo) {
    size_t idx = (size_t)blockIdx.x * 256 + threadIdx.x;   // float4 index
    int i = (int)(idx >> 9);
    int j = ((int)(idx & 511)) << 2;
    size_t off = (size_t)i * N + j;
    float4 l = *(const float4*)(L + off);
    float m[4] = {l.x, l.y, l.z, l.w};
    float t0[4] = {0.f, 0.f, 0.f, 0.f};
#pragma unroll
    for (int c = 0; c < 4; c++)
        if (j + c == i) { m[c] -= 1.0f; t0[c] = 1.0f; }
    *(float4*)(T0 + off) = make_float4(t0[0], t0[1], t0[2], t0[3]);
    *(float4*)(T1 + off) = make_float4(m[0], m[1], m[2], m[3]);
#pragma unroll
    for (int c = 0; c < 4; c++) {
        split_store(m[c],        T1hi + off + c, T1lo + off + c);
        split_store(2.0f * m[c], Fhi + off + c,  Flo + off + c);
    }
}

// ---------------------------------------------------------------------------
// HMMA GEMM step: Tout = F @ B - Cold  (emulated fp32 via bf16 hi/lo, 3 products)
// CTA 128x128, 256 thr (8 warps 2x4, warp tile 64x32), BK=32, double-buffered
// cp.async. Smem rows padded to 80B -> conflict-free ldmatrix.
// ---------------------------------------------------------------------------
constexpr uint32_t PITCH = 80;                 // bytes per 32-bf16 row (64+16 pad)
constexpr uint32_t SZ_A  = 128 * PITCH;        // 10240 per operand array
constexpr uint32_t STAGE = 4 * SZ_A;           // Ahi, Alo, Bhi, Blo
constexpr uint32_t SMEM_GEMM = 2 * STAGE;      // 81920

__global__ void __launch_bounds__(256, 2)
cheb_hmma(const __nv_bfloat16* __restrict__ Ahi_g, const __nv_bfloat16* __restrict__ Alo_g,
          const __nv_bfloat16* __restrict__ Bhi_g, const __nv_bfloat16* __restrict__ Blo_g,
          const float* __restrict__ Cold, float* __restrict__ Tout,
          __nv_bfloat16* __restrict__ HiOut, __nv_bfloat16* __restrict__ LoOut) {
    extern __shared__ char smem[];
    const uint32_t sb = smem_u32(smem);
    const int tid = threadIdx.x, lane = tid & 31, wid = tid >> 5;
    const int wm = wid >> 2, wn = wid & 3;
    const int row0 = blockIdx.y * 128, col0 = blockIdx.x * 128;

    // producer mapping: thread t handles row t/2, 32B half (t&1) of each 64B chunk
    const int prow = tid >> 1;
    const uint32_t pcol = (uint32_t)(tid & 1) * 32;
    const char* gAh = (const char*)Ahi_g + (size_t)(row0 + prow) * 4096 + pcol;
    const char* gAl = (const char*)Alo_g + (size_t)(row0 + prow) * 4096 + pcol;
    const char* gBh = (const char*)Bhi_g + (size_t)(col0 + prow) * 4096 + pcol;
    const char* gBl = (const char*)Blo_g + (size_t)(col0 + prow) * 4096 + pcol;
    const uint32_t sArow = (uint32_t)prow * PITCH + pcol;

    auto load_chunk = [&](int stg, int ch) {
        const uint32_t base = sb + (uint32_t)stg * STAGE + sArow;
        const uint32_t go = (uint32_t)ch * 64;
        cp16(base,                 gAh + go);
        cp16(base + 16,            gAh + go + 16);
        cp16(base + SZ_A,          gAl + go);
        cp16(base + SZ_A + 16,     gAl + go + 16);
        cp16(base + 2 * SZ_A,      gBh + go);
        cp16(base + 2 * SZ_A + 16, gBh + go + 16);
        cp16(base + 3 * SZ_A,      gBl + go);
        cp16(base + 3 * SZ_A + 16, gBl + go + 16);
        CP_COMMIT();
    };

    float acc[4][4][4];
#pragma unroll
    for (int i = 0; i < 4; i++)
#pragma unroll
        for (int j = 0; j < 4; j++)
#pragma unroll
            for (int r = 0; r < 4; r++) acc[i][j][r] = 0.f;

    // ldmatrix lane->address offsets (A: a0..a3 frag order; B: x4 = two n8 frags)
    const uint32_t aoff = (uint32_t)((lane & 7) + ((lane >> 3) & 1) * 8) * PITCH
                        + (uint32_t)(lane >> 4) * 16;
    const uint32_t boff = (uint32_t)((lane & 7) + ((lane >> 4) & 1) * 8) * PITCH
                        + (uint32_t)((lane >> 3) & 1) * 16;

    load_chunk(0, 0);
    load_chunk(1, 1);

    constexpr int NCH = N / 32;   // 64
    for (int ch = 0; ch < NCH; ch++) {
        const int stg = ch & 1;
        if (ch < NCH - 2) asm volatile("cp.async.wait_group 1;" ::: "memory");
        else              asm volatile("cp.async.wait_group 0;" ::: "memory");
        __syncthreads();
        const uint32_t base = sb + (uint32_t)stg * STAGE;
#pragma unroll
        for (int kc = 0; kc < 2; kc++) {
            const uint32_t ahb = base + (uint32_t)(wm * 64) * PITCH + kc * 32 + aoff;
            uint32_t ah[4][4], al[4][4];
#pragma unroll
            for (int mt = 0; mt < 4; mt++) {
                ldsm4(ah[mt], ahb + mt * 16 * PITCH);
                ldsm4(al[mt], ahb + mt * 16 * PITCH + SZ_A);
            }
#pragma unroll
            for (int bt = 0; bt < 2; bt++) {
                const uint32_t bhb = base + 2 * SZ_A
                                   + (uint32_t)(wn * 32 + bt * 16) * PITCH + kc * 32 + boff;
                uint32_t bh[4], bl[4];
                ldsm4(bh, bhb);
                ldsm4(bl, bhb + SZ_A);
#pragma unroll
                for (int mt = 0; mt < 4; mt++) {
                    mma_bf16(acc[mt][2 * bt],     ah[mt], bh[0], bh[1]);
                    mma_bf16(acc[mt][2 * bt + 1], ah[mt], bh[2], bh[3]);
                    mma_bf16(acc[mt][2 * bt],     ah[mt], bl[0], bl[1]);
                    mma_bf16(acc[mt][2 * bt + 1], ah[mt], bl[2], bl[3]);
                    mma_bf16(acc[mt][2 * bt],     al[mt], bh[0], bh[1]);
                    mma_bf16(acc[mt][2 * bt + 1], al[mt], bh[2], bh[3]);
                }
            }
        }
        __syncthreads();
        if (ch + 2 < NCH) load_chunk(stg, ch + 2);
    }

    // Epilogue: v = acc - Cold; write fp32 + bf16 hi/lo split for next step
#pragma unroll
    for (int mt = 0; mt < 4; mt++) {
        const int r = row0 + wm * 64 + mt * 16 + (lane >> 2);
#pragma unroll
        for (int nt = 0; nt < 4; nt++) {
            const int c = col0 + wn * 32 + nt * 8 + (lane & 3) * 2;
            const size_t o0 = (size_t)r * N + c;
            const size_t o1 = o0 + (size_t)8 * N;
            const float2 c0 = *(const float2*)(Cold + o0);
            const float2 c1 = *(const float2*)(Cold + o1);
            const float v0 = acc[mt][nt][0] - c0.x;
            const float v1 = acc[mt][nt][1] - c0.y;
            const float v2 = acc[mt][nt][2] - c1.x;
            const float v3 = acc[mt][nt][3] - c1.y;
            *(float2*)(Tout + o0) = make_float2(v0, v1);
            *(float2*)(Tout + o1) = make_float2(v2, v3);
            const __nv_bfloat16 h0 = __float2bfloat16(v0), h1 = __float2bfloat16(v1);
            const __nv_bfloat16 h2 = __float2bfloat16(v2), h3 = __float2bfloat16(v3);
            *(__nv_bfloat162*)(HiOut + o0) = __halves2bfloat162(h0, h1);
            *(__nv_bfloat162*)(HiOut + o1) = __halves2bfloat162(h2, h3);
            *(__nv_bfloat162*)(LoOut + o0) = __halves2bfloat162(
                __float2bfloat16(v0 - __bfloat162float(h0)),
                __float2bfloat16(v1 - __bfloat162float(h1)));
            *(__nv_bfloat162*)(LoOut + o1) = __halves2bfloat162(
                __float2bfloat16(v2 - __bfloat162float(h2)),
                __float2bfloat16(v3 - __bfloat162float(h3)));
        }
    }
}

// ---------------------------------------------------------------------------
// Finalize: out[f*N+i][j] = sum_k cw[k][f] * T_k[i][j]
// ---------------------------------------------------------------------------
__global__ void __launch_bounds__(256)
cheb_finalize(const float* __restrict__ Ts, const float* __restrict__ cw,
              float* __restrict__ out) {
    __shared__ float cws[NCOEF * NF];
    if (threadIdx.x < NCOEF * NF) cws[threadIdx.x] = cw[threadIdx.x];
    __syncthreads();

    size_t idx = (size_t)blockIdx.x * 256 + threadIdx.x;
    int i = (int)(idx >> 9);
    int j = ((int)(idx & 511)) << 2;
    size_t off = (size_t)i * N + j;

    float4 t[NCOEF];
#pragma unroll
    for (int k = 0; k < NCOEF; k++)
        t[k] = *(const float4*)(Ts + (size_t)k * NN + off);

#pragma unroll
    for (int f = 0; f < NF; f++) {
        float4 s = make_float4(0.f, 0.f, 0.f, 0.f);
#pragma unroll
        for (int k = 0; k < NCOEF; k++) {
            float c = cws[k * NF + f];
            s.x += c * t[k].x; s.y += c * t[k].y;
            s.z += c * t[k].z; s.w += c * t[k].w;
        }
        *(float4*)(out + (size_t)f * NN + off) = s;
    }
}

// ---------------------------------------------------------------------------
// Launch (graph-capturable, allocation-free)
// ---------------------------------------------------------------------------
extern "C" void kernel_launch(void* const* d_in, const int* in_sizes, int n_in,
                              void* d_out, int out_size) {
    const float* L    = (const float*)d_in[0];
    const float* taus = (const float*)d_in[1];
    float* out = (float*)d_out;

    float *Ts, *cw;
    __nv_bfloat16 *hi, *lo, *Fhi, *Flo;
    cudaGetSymbolAddress((void**)&Ts, g_Ts);
    cudaGetSymbolAddress((void**)&cw, g_cw);
    cudaGetSymbolAddress((void**)&hi, g_hi);
    cudaGetSymbolAddress((void**)&lo, g_lo);
    cudaGetSymbolAddress((void**)&Fhi, g_Fhi);
    cudaGetSymbolAddress((void**)&Flo, g_Flo);

    cudaFuncSetAttribute(cheb_hmma, cudaFuncAttributeMaxDynamicSharedMemorySize,
                         SMEM_GEMM);

    cheb_coeff<<<1, 160>>>(taus, cw);
    cheb_prep<<<(int)(NN / 4 / 256), 256>>>(L, Ts, Ts + NN,
                                            hi + NN, lo + NN, Fhi, Flo);

    dim3 grid(N / 128, N / 128), block(256);
    for (int k = 2; k <= ORDER; k++) {
        cheb_hmma<<<grid, block, SMEM_GEMM>>>(
            Fhi, Flo,
            hi + (size_t)(k - 1) * NN, lo + (size_t)(k - 1) * NN,   // B = T_{k-1}
            Ts + (size_t)(k - 2) * NN,                              // Cold = T_{k-2}
            Ts + (size_t)k * NN,                                    // T_k fp32
            hi + (size_t)k * NN, lo + (size_t)k * NN);              // T_k split
    }
    cheb_finalize<<<(int)(NN / 4 / 256), 256>>>(Ts, cw, out);
}

// round 4
// speedup vs baseline: 2.3006x; 1.0861x over previous
#include <cuda_runtime.h>
#include <cuda_bf16.h>
#include <math.h>
#include <cstdint>

// Problem constants (fixed): N=2048, NF=8, order=16, LMAX=2 => a1=a2=1
constexpr int N = 2048;
constexpr int NF = 8;
constexpr int ORDER = 16;
constexpr int NCOEF = ORDER + 1;          // 17
constexpr size_t NN = (size_t)N * N;      // 4M elems

// Scratch (__device__ globals = sanctioned, no cudaMalloc)
__device__ float         g_Ts[(size_t)NCOEF * NN];   // T_0..T_16 fp32 (272MB)
__device__ __nv_bfloat16 g_hi[(size_t)NCOEF * NN];   // bf16 hi of T_k
__device__ __nv_bfloat16 g_lo[(size_t)NCOEF * NN];   // bf16 lo of T_k
__device__ __nv_bfloat16 g_Fhi[NN];                  // F = 2(L-I) split
__device__ __nv_bfloat16 g_Flo[NN];
__device__ float         g_cw[NCOEF * NF];

// ---------------------------------------------------------------------------
// PTX helpers (arch-neutral sm_80+ only; harness targets plain sm_100)
// ---------------------------------------------------------------------------
__device__ __forceinline__ uint32_t smem_u32(const void* p) {
    uint32_t a;
    asm("{ .reg .u64 t; cvta.to.shared.u64 t, %1; cvt.u32.u64 %0, t; }" : "=r"(a) : "l"(p));
    return a;
}
__device__ __forceinline__ void cp16(uint32_t dst, const void* src) {
    asm volatile("cp.async.cg.shared.global [%0], [%1], 16;" :: "r"(dst), "l"(src));
}
#define CP_COMMIT() asm volatile("cp.async.commit_group;" ::: "memory")

__device__ __forceinline__ void ldsm4(uint32_t (&r)[4], uint32_t addr) {
    asm volatile("ldmatrix.sync.aligned.m8n8.x4.shared.b16 {%0,%1,%2,%3}, [%4];"
                 : "=r"(r[0]), "=r"(r[1]), "=r"(r[2]), "=r"(r[3]) : "r"(addr));
}
__device__ __forceinline__ void mma_bf16(float (&d)[4], const uint32_t (&a)[4],
                                         uint32_t b0, uint32_t b1) {
    asm volatile("mma.sync.aligned.m16n8k16.row.col.f32.bf16.bf16.f32 "
                 "{%0,%1,%2,%3},{%4,%5,%6,%7},{%8,%9},{%0,%1,%2,%3};"
                 : "+f"(d[0]), "+f"(d[1]), "+f"(d[2]), "+f"(d[3])
                 : "r"(a[0]), "r"(a[1]), "r"(a[2]), "r"(a[3]), "r"(b0), "r"(b1));
}

// 128B XOR swizzle on a 64B-pitch row layout (16B-granular, alignment-safe)
__device__ __forceinline__ uint32_t swz(uint32_t off) {
    return off ^ (((off >> 7) & 7u) << 4);
}

// ---------------------------------------------------------------------------
// Chebyshev coefficients (cw[0] pre-scaled by 0.5)
// ---------------------------------------------------------------------------
__global__ void cheb_coeff(const float* __restrict__ taus, float* __restrict__ cw) {
    int t = threadIdx.x;
    if (t < NCOEF * NF) {
        int k = t >> 3, f = t & 7;
        double tau = (double)taus[f];
        const double PI = 3.14159265358979323846;
        double s = 0.0;
        for (int n = 0; n < NCOEF; n++) {
            double arg = (n + 0.5) / (double)NCOEF;
            s += cos(PI * (double)k * arg) * exp(-(cos(PI * arg) + 1.0) * tau);
        }
        double v = (2.0 / (double)NCOEF) * s;
        if (k == 0) v *= 0.5;
        cw[t] = (float)v;
    }
}

// ---------------------------------------------------------------------------
// Prep: T0=I, T1=L-I (+bf16 split), F=2(L-I) as bf16 split
// ---------------------------------------------------------------------------
__device__ __forceinline__ void split_store(float x, __nv_bfloat16* hi, __nv_bfloat16* lo) {
    __nv_bfloat16 h = __float2bfloat16(x);
    *hi = h;
    *lo = __float2bfloat16(x - __bfloat162float(h));
}

__global__ void __launch_bounds__(256)
cheb_prep(const float* __restrict__ L, float* __restrict__ T0, float* __restrict__ T1,
          __nv_bfloat16* __restrict__ T1hi, __nv_bfloat16* __restrict__ T1lo,
          __nv_bfloat16* __restrict__ Fhi, __nv_bfloat16* __restrict__ Flo) {
    size_t idx = (size_t)blockIdx.x * 256 + threadIdx.x;   // float4 index
    int i = (int)(idx >> 9);
    int j = ((int)(idx & 511)) << 2;
    size_t off = (size_t)i * N + j;
    float4 l = *(const float4*)(L + off);
    float m[4] = {l.x, l.y, l.z, l.w};
    float t0[4] = {0.f, 0.f, 0.f, 0.f};
#pragma unroll
    for (int c = 0; c < 4; c++)
        if (j + c == i) { m[c] -= 1.0f; t0[c] = 1.0f; }
    *(float4*)(T0 + off) = make_float4(t0[0], t0[1], t0[2], t0[3]);
    *(float4*)(T1 + off) = make_float4(m[0], m[1], m[2], m[3]);
#pragma unroll
    for (int c = 0; c < 4; c++) {
        split_store(m[c],        T1hi + off + c, T1lo + off + c);
        split_store(2.0f * m[c], Fhi + off + c,  Flo + off + c);
    }
}

// ---------------------------------------------------------------------------
// HMMA GEMM step: Tout = F @ B - Cold  (emulated fp32 via bf16 hi/lo, 3 products)
// CTA 128x128, 256 thr (8 warps 2x4, warp tile 64x32), BK=32.
// 3-stage cp.async pipeline, ONE __syncthreads per chunk, XOR-swizzled smem.
// ---------------------------------------------------------------------------
constexpr uint32_t SZ_A  = 128 * 64;           // 8192 B per operand array
constexpr uint32_t STAGE = 4 * SZ_A;           // Ahi, Alo, Bhi, Blo = 32768
constexpr uint32_t SMEM_GEMM = 3 * STAGE;      // 98304

__global__ void __launch_bounds__(256, 2)
cheb_hmma(const __nv_bfloat16* __restrict__ Ahi_g, const __nv_bfloat16* __restrict__ Alo_g,
          const __nv_bfloat16* __restrict__ Bhi_g, const __nv_bfloat16* __restrict__ Blo_g,
          const float* __restrict__ Cold, float* __restrict__ Tout,
          __nv_bfloat16* __restrict__ HiOut, __nv_bfloat16* __restrict__ LoOut) {
    extern __shared__ char smem[];
    const uint32_t sb = smem_u32(smem);
    const int tid = threadIdx.x, lane = tid & 31, wid = tid >> 5;
    const int wm = wid >> 2, wn = wid & 3;
    const int row0 = blockIdx.y * 128, col0 = blockIdx.x * 128;

    // producer mapping: thread t handles row t/2, 32B half (t&1); two 16B pieces
    const int prow = tid >> 1;
    const uint32_t pcol = (uint32_t)(tid & 1) * 32;
    const char* gAh = (const char*)Ahi_g + (size_t)(row0 + prow) * 4096 + pcol;
    const char* gAl = (const char*)Alo_g + (size_t)(row0 + prow) * 4096 + pcol;
    const char* gBh = (const char*)Bhi_g + (size_t)(col0 + prow) * 4096 + pcol;
    const char* gBl = (const char*)Blo_g + (size_t)(col0 + prow) * 4096 + pcol;
    const uint32_t s0 = swz((uint32_t)prow * 64 + pcol);
    const uint32_t s1 = swz((uint32_t)prow * 64 + pcol + 16);

    auto load_chunk = [&](int stg, int ch) {
        const uint32_t base = sb + (uint32_t)stg * STAGE;
        const uint32_t go = (uint32_t)ch * 64;
        cp16(base + s0,              gAh + go);
        cp16(base + s1,              gAh + go + 16);
        cp16(base + SZ_A + s0,       gAl + go);
        cp16(base + SZ_A + s1,       gAl + go + 16);
        cp16(base + 2 * SZ_A + s0,   gBh + go);
        cp16(base + 2 * SZ_A + s1,   gBh + go + 16);
        cp16(base + 3 * SZ_A + s0,   gBl + go);
        cp16(base + 3 * SZ_A + s1,   gBl + go + 16);
        CP_COMMIT();
    };

    float acc[4][4][4];
#pragma unroll
    for (int i = 0; i < 4; i++)
#pragma unroll
        for (int j = 0; j < 4; j++)
#pragma unroll
            for (int r = 0; r < 4; r++) acc[i][j][r] = 0.f;

    // ldmatrix lane offsets (row within 16-row tile, 16B column select)
    const uint32_t arow = (uint32_t)((lane & 7) + ((lane >> 3) & 1) * 8);
    const uint32_t acol = (uint32_t)(lane >> 4) * 16;
    const uint32_t brow = (uint32_t)((lane & 7) + ((lane >> 4) & 1) * 8);
    const uint32_t bcol = (uint32_t)((lane >> 3) & 1) * 16;

    load_chunk(0, 0);
    load_chunk(1, 1);

    constexpr int NCH = N / 32;   // 64
    for (int ch = 0; ch < NCH; ch++) {
        const int stg = ch % 3;
        if (ch < NCH - 1) asm volatile("cp.async.wait_group 1;" ::: "memory");
        else              asm volatile("cp.async.wait_group 0;" ::: "memory");
        __syncthreads();
        if (ch + 2 < NCH) load_chunk((ch + 2) % 3, ch + 2);   // overlap with MMAs

        const uint32_t base = sb + (uint32_t)stg * STAGE;
#pragma unroll
        for (int kc = 0; kc < 2; kc++) {
            uint32_t ah[4][4], al[4][4];
#pragma unroll
            for (int mt = 0; mt < 4; mt++) {
                const uint32_t off = ((uint32_t)(wm * 64 + mt * 16) + arow) * 64
                                   + (uint32_t)kc * 32 + acol;
                ldsm4(ah[mt], base + swz(off));
                ldsm4(al[mt], base + SZ_A + swz(off));
            }
#pragma unroll
            for (int bt = 0; bt < 2; bt++) {
                const uint32_t offb = ((uint32_t)(wn * 32 + bt * 16) + brow) * 64
                                    + (uint32_t)kc * 32 + bcol;
                uint32_t bh[4], bl[4];
                ldsm4(bh, base + 2 * SZ_A + swz(offb));
                ldsm4(bl, base + 3 * SZ_A + swz(offb));
                // product-major: same-acc dependency distance = 8 MMAs
#pragma unroll
                for (int mt = 0; mt < 4; mt++) {
                    mma_bf16(acc[mt][2 * bt],     ah[mt], bh[0], bh[1]);
                    mma_bf16(acc[mt][2 * bt + 1], ah[mt], bh[2], bh[3]);
                }
#pragma unroll
                for (int mt = 0; mt < 4; mt++) {
                    mma_bf16(acc[mt][2 * bt],     ah[mt], bl[0], bl[1]);
                    mma_bf16(acc[mt][2 * bt + 1], ah[mt], bl[2], bl[3]);
                }
#pragma unroll
                for (int mt = 0; mt < 4; mt++) {
                    mma_bf16(acc[mt][2 * bt],     al[mt], bh[0], bh[1]);
                    mma_bf16(acc[mt][2 * bt + 1], al[mt], bh[2], bh[3]);
                }
            }
        }
    }

    // Epilogue: v = acc - Cold; write fp32 + bf16 hi/lo split for next step
#pragma unroll
    for (int mt = 0; mt < 4; mt++) {
        const int r = row0 + wm * 64 + mt * 16 + (lane >> 2);
#pragma unroll
        for (int nt = 0; nt < 4; nt++) {
            const int c = col0 + wn * 32 + nt * 8 + (lane & 3) * 2;
            const size_t o0 = (size_t)r * N + c;
            const size_t o1 = o0 + (size_t)8 * N;
            const float2 c0 = *(const float2*)(Cold + o0);
            const float2 c1 = *(const float2*)(Cold + o1);
            const float v0 = acc[mt][nt][0] - c0.x;
            const float v1 = acc[mt][nt][1] - c0.y;
            const float v2 = acc[mt][nt][2] - c1.x;
            const float v3 = acc[mt][nt][3] - c1.y;
            *(float2*)(Tout + o0) = make_float2(v0, v1);
            *(float2*)(Tout + o1) = make_float2(v2, v3);
            const __nv_bfloat16 h0 = __float2bfloat16(v0), h1 = __float2bfloat16(v1);
            const __nv_bfloat16 h2 = __float2bfloat16(v2), h3 = __float2bfloat16(v3);
            *(__nv_bfloat162*)(HiOut + o0) = __halves2bfloat162(h0, h1);
            *(__nv_bfloat162*)(HiOut + o1) = __halves2bfloat162(h2, h3);
            *(__nv_bfloat162*)(LoOut + o0) = __halves2bfloat162(
                __float2bfloat16(v0 - __bfloat162float(h0)),
                __float2bfloat16(v1 - __bfloat162float(h1)));
            *(__nv_bfloat162*)(LoOut + o1) = __halves2bfloat162(
                __float2bfloat16(v2 - __bfloat162float(h2)),
                __float2bfloat16(v3 - __bfloat162float(h3)));
        }
    }
}

// ---------------------------------------------------------------------------
// Finalize: out[f*N+i][j] = sum_k cw[k][f] * T_k[i][j]
// ---------------------------------------------------------------------------
__global__ void __launch_bounds__(256)
cheb_finalize(const float* __restrict__ Ts, const float* __restrict__ cw,
              float* __restrict__ out) {
    __shared__ float cws[NCOEF * NF];
    if (threadIdx.x < NCOEF * NF) cws[threadIdx.x] = cw[threadIdx.x];
    __syncthreads();

    size_t idx = (size_t)blockIdx.x * 256 + threadIdx.x;
    int i = (int)(idx >> 9);
    int j = ((int)(idx & 511)) << 2;
    size_t off = (size_t)i * N + j;

    float4 t[NCOEF];
#pragma unroll
    for (int k = 0; k < NCOEF; k++)
        t[k] = *(const float4*)(Ts + (size_t)k * NN + off);

#pragma unroll
    for (int f = 0; f < NF; f++) {
        float4 s = make_float4(0.f, 0.f, 0.f, 0.f);
#pragma unroll
        for (int k = 0; k < NCOEF; k++) {
            float c = cws[k * NF + f];
            s.x += c * t[k].x; s.y += c * t[k].y;
            s.z += c * t[k].z; s.w += c * t[k].w;
        }
        *(float4*)(out + (size_t)f * NN + off) = s;
    }
}

// ---------------------------------------------------------------------------
// Launch (graph-capturable, allocation-free)
// ---------------------------------------------------------------------------
extern "C" void kernel_launch(void* const* d_in, const int* in_sizes, int n_in,
                              void* d_out, int out_size) {
    const float* L    = (const float*)d_in[0];
    const float* taus = (const float*)d_in[1];
    float* out = (float*)d_out;

    float *Ts, *cw;
    __nv_bfloat16 *hi, *lo, *Fhi, *Flo;
    cudaGetSymbolAddress((void**)&Ts, g_Ts);
    cudaGetSymbolAddress((void**)&cw, g_cw);
    cudaGetSymbolAddress((void**)&hi, g_hi);
    cudaGetSymbolAddress((void**)&lo, g_lo);
    cudaGetSymbolAddress((void**)&Fhi, g_Fhi);
    cudaGetSymbolAddress((void**)&Flo, g_Flo);

    cudaFuncSetAttribute(cheb_hmma, cudaFuncAttributeMaxDynamicSharedMemorySize,
                         SMEM_GEMM);

    cheb_coeff<<<1, 160>>>(taus, cw);
    cheb_prep<<<(int)(NN / 4 / 256), 256>>>(L, Ts, Ts + NN,
                                            hi + NN, lo + NN, Fhi, Flo);

    dim3 grid(N / 128, N / 128), block(256);
    for (int k = 2; k <= ORDER; k++) {
        cheb_hmma<<<grid, block, SMEM_GEMM>>>(
            Fhi, Flo,
            hi + (size_t)(k - 1) * NN, lo + (size_t)(k - 1) * NN,   // B = T_{k-1}
            Ts + (size_t)(k - 2) * NN,                              // Cold = T_{k-2}
            Ts + (size_t)k * NN,                                    // T_k fp32
            hi + (size_t)k * NN, lo + (size_t)k * NN);              // T_k split
    }
    cheb_finalize<<<(int)(NN / 4 / 256), 256>>>(Ts, cw, out);
}

// round 5
// speedup vs baseline: 3.1542x; 1.3710x over previous
#include <cuda_runtime.h>
#include <cuda_bf16.h>
#include <math.h>
#include <cstdint>

// Problem constants (fixed): N=2048, NF=8, order=16, LMAX=2 => a1=a2=1
constexpr int N = 2048;
constexpr int NF = 8;
constexpr int ORDER = 16;
constexpr int NCOEF = ORDER + 1;          // 17
constexpr size_t NN = (size_t)N * N;      // 4M elems

// Scratch (__device__ globals = sanctioned, no cudaMalloc)
__device__ float         g_Ts[(size_t)NCOEF * NN];   // T_0..T_16 fp32 (272MB)
__device__ __nv_bfloat16 g_hi[(size_t)NCOEF * NN];   // bf16 hi of T_k
__device__ __nv_bfloat16 g_lo[(size_t)NCOEF * NN];   // bf16 lo of T_k
__device__ __nv_bfloat16 g_Fhi[NN];                  // F = 2(L-I), bf16 hi only
__device__ float         g_cw[NCOEF * NF];

// ---------------------------------------------------------------------------
// PTX helpers (arch-neutral sm_80+ only; harness targets plain sm_100)
// ---------------------------------------------------------------------------
__device__ __forceinline__ uint32_t smem_u32(const void* p) {
    uint32_t a;
    asm("{ .reg .u64 t; cvta.to.shared.u64 t, %1; cvt.u32.u64 %0, t; }" : "=r"(a) : "l"(p));
    return a;
}
__device__ __forceinline__ void cp16(uint32_t dst, const void* src) {
    asm volatile("cp.async.cg.shared.global [%0], [%1], 16;" :: "r"(dst), "l"(src));
}
#define CP_COMMIT() asm volatile("cp.async.commit_group;" ::: "memory")

__device__ __forceinline__ void ldsm4(uint32_t (&r)[4], uint32_t addr) {
    asm volatile("ldmatrix.sync.aligned.m8n8.x4.shared.b16 {%0,%1,%2,%3}, [%4];"
                 : "=r"(r[0]), "=r"(r[1]), "=r"(r[2]), "=r"(r[3]) : "r"(addr));
}
__device__ __forceinline__ void mma_bf16(float (&d)[4], const uint32_t (&a)[4],
                                         uint32_t b0, uint32_t b1) {
    asm volatile("mma.sync.aligned.m16n8k16.row.col.f32.bf16.bf16.f32 "
                 "{%0,%1,%2,%3},{%4,%5,%6,%7},{%8,%9},{%0,%1,%2,%3};"
                 : "+f"(d[0]), "+f"(d[1]), "+f"(d[2]), "+f"(d[3])
                 : "r"(a[0]), "r"(a[1]), "r"(a[2]), "r"(a[3]), "r"(b0), "r"(b1));
}

// 128B XOR swizzle on a 64B-pitch row layout (16B-granular, alignment-safe)
__device__ __forceinline__ uint32_t swz(uint32_t off) {
    return off ^ (((off >> 7) & 7u) << 4);
}

// ---------------------------------------------------------------------------
// Chebyshev coefficients (cw[0] pre-scaled by 0.5)
// ---------------------------------------------------------------------------
__global__ void cheb_coeff(const float* __restrict__ taus, float* __restrict__ cw) {
    int t = threadIdx.x;
    if (t < NCOEF * NF) {
        int k = t >> 3, f = t & 7;
        double tau = (double)taus[f];
        const double PI = 3.14159265358979323846;
        double s = 0.0;
        for (int n = 0; n < NCOEF; n++) {
            double arg = (n + 0.5) / (double)NCOEF;
            s += cos(PI * (double)k * arg) * exp(-(cos(PI * arg) + 1.0) * tau);
        }
        double v = (2.0 / (double)NCOEF) * s;
        if (k == 0) v *= 0.5;
        cw[t] = (float)v;
    }
}

// ---------------------------------------------------------------------------
// Prep: T0=I, T1=L-I (+bf16 split), F=2(L-I) hi only
// ---------------------------------------------------------------------------
__device__ __forceinline__ void split_store(float x, __nv_bfloat16* hi, __nv_bfloat16* lo) {
    __nv_bfloat16 h = __float2bfloat16(x);
    *hi = h;
    *lo = __float2bfloat16(x - __bfloat162float(h));
}

__global__ void __launch_bounds__(256)
cheb_prep(const float* __restrict__ L, float* __restrict__ T0, float* __restrict__ T1,
          __nv_bfloat16* __restrict__ T1hi, __nv_bfloat16* __restrict__ T1lo,
          __nv_bfloat16* __restrict__ Fhi) {
    size_t idx = (size_t)blockIdx.x * 256 + threadIdx.x;   // float4 index
    int i = (int)(idx >> 9);
    int j = ((int)(idx & 511)) << 2;
    size_t off = (size_t)i * N + j;
    float4 l = *(const float4*)(L + off);
    float m[4] = {l.x, l.y, l.z, l.w};
    float t0[4] = {0.f, 0.f, 0.f, 0.f};
#pragma unroll
    for (int c = 0; c < 4; c++)
        if (j + c == i) { m[c] -= 1.0f; t0[c] = 1.0f; }
    *(float4*)(T0 + off) = make_float4(t0[0], t0[1], t0[2], t0[3]);
    *(float4*)(T1 + off) = make_float4(m[0], m[1], m[2], m[3]);
#pragma unroll
    for (int c = 0; c < 4; c++) {
        split_store(m[c], T1hi + off + c, T1lo + off + c);
        Fhi[off + c] = __float2bfloat16(2.0f * m[c]);
    }
}

// ---------------------------------------------------------------------------
// HMMA GEMM step: Tout = Fh @ B - Cold  (2-product: Ah*Bh + Ah*Bl; B 16-bit)
// CTA 128x128, 256 thr (8 warps 2x4, warp tile 64x32), BK=32.
// 4-stage cp.async pipeline, ONE __syncthreads per chunk, XOR-swizzled smem.
// ---------------------------------------------------------------------------
constexpr uint32_t SZ_A  = 128 * 64;           // 8192 B per operand array
constexpr uint32_t STAGE = 3 * SZ_A;           // Ah, Bh, Bl = 24576
constexpr uint32_t SMEM_GEMM = 4 * STAGE;      // 98304

__global__ void __launch_bounds__(256, 2)
cheb_hmma(const __nv_bfloat16* __restrict__ Ahi_g,
          const __nv_bfloat16* __restrict__ Bhi_g, const __nv_bfloat16* __restrict__ Blo_g,
          const float* __restrict__ Cold, float* __restrict__ Tout,
          __nv_bfloat16* __restrict__ HiOut, __nv_bfloat16* __restrict__ LoOut) {
    extern __shared__ char smem[];
    const uint32_t sb = smem_u32(smem);
    const int tid = threadIdx.x, lane = tid & 31, wid = tid >> 5;
    const int wm = wid >> 2, wn = wid & 3;
    const int row0 = blockIdx.y * 128, col0 = blockIdx.x * 128;

    // producer mapping: thread t handles row t/2, 32B half (t&1); two 16B pieces
    const int prow = tid >> 1;
    const uint32_t pcol = (uint32_t)(tid & 1) * 32;
    const char* gAh = (const char*)Ahi_g + (size_t)(row0 + prow) * 4096 + pcol;
    const char* gBh = (const char*)Bhi_g + (size_t)(col0 + prow) * 4096 + pcol;
    const char* gBl = (const char*)Blo_g + (size_t)(col0 + prow) * 4096 + pcol;
    const uint32_t s0 = swz((uint32_t)prow * 64 + pcol);
    const uint32_t s1 = swz((uint32_t)prow * 64 + pcol + 16);

    auto load_chunk = [&](int stg, int ch) {
        const uint32_t base = sb + (uint32_t)stg * STAGE;
        const uint32_t go = (uint32_t)ch * 64;
        cp16(base + s0,              gAh + go);
        cp16(base + s1,              gAh + go + 16);
        cp16(base + SZ_A + s0,       gBh + go);
        cp16(base + SZ_A + s1,       gBh + go + 16);
        cp16(base + 2 * SZ_A + s0,   gBl + go);
        cp16(base + 2 * SZ_A + s1,   gBl + go + 16);
        CP_COMMIT();
    };

    float acc[4][4][4];
#pragma unroll
    for (int i = 0; i < 4; i++)
#pragma unroll
        for (int j = 0; j < 4; j++)
#pragma unroll
            for (int r = 0; r < 4; r++) acc[i][j][r] = 0.f;

    // ldmatrix lane offsets (row within 16-row tile, 16B column select)
    const uint32_t arow = (uint32_t)((lane & 7) + ((lane >> 3) & 1) * 8);
    const uint32_t acol = (uint32_t)(lane >> 4) * 16;
    const uint32_t brow = (uint32_t)((lane & 7) + ((lane >> 4) & 1) * 8);
    const uint32_t bcol = (uint32_t)((lane >> 3) & 1) * 16;

    load_chunk(0, 0);
    load_chunk(1, 1);
    load_chunk(2, 2);

    constexpr int NCH = N / 32;   // 64
    for (int ch = 0; ch < NCH; ch++) {
        const int stg = ch & 3;
        const int rem = NCH - 1 - ch;   // chunks still pending beyond this one
        if (rem >= 2)      asm volatile("cp.async.wait_group 2;" ::: "memory");
        else if (rem == 1) asm volatile("cp.async.wait_group 1;" ::: "memory");
        else               asm volatile("cp.async.wait_group 0;" ::: "memory");
        __syncthreads();
        if (ch + 3 < NCH) load_chunk((ch + 3) & 3, ch + 3);   // overlap with MMAs

        const uint32_t base = sb + (uint32_t)stg * STAGE;
#pragma unroll
        for (int kc = 0; kc < 2; kc++) {
            uint32_t ah[4][4];
#pragma unroll
            for (int mt = 0; mt < 4; mt++) {
                const uint32_t off = ((uint32_t)(wm * 64 + mt * 16) + arow) * 64
                                   + (uint32_t)kc * 32 + acol;
                ldsm4(ah[mt], base + swz(off));
            }
#pragma unroll
            for (int bt = 0; bt < 2; bt++) {
                const uint32_t offb = ((uint32_t)(wn * 32 + bt * 16) + brow) * 64
                                    + (uint32_t)kc * 32 + bcol;
                uint32_t bh[4], bl[4];
                ldsm4(bh, base + SZ_A + swz(offb));
                ldsm4(bl, base + 2 * SZ_A + swz(offb));
                // product-major: same-acc dependency distance = 8 MMAs
#pragma unroll
                for (int mt = 0; mt < 4; mt++) {
                    mma_bf16(acc[mt][2 * bt],     ah[mt], bh[0], bh[1]);
                    mma_bf16(acc[mt][2 * bt + 1], ah[mt], bh[2], bh[3]);
                }
#pragma unroll
                for (int mt = 0; mt < 4; mt++) {
                    mma_bf16(acc[mt][2 * bt],     ah[mt], bl[0], bl[1]);
                    mma_bf16(acc[mt][2 * bt + 1], ah[mt], bl[2], bl[3]);
                }
            }
        }
    }

    // Epilogue: v = acc - Cold; write fp32 + bf16 hi/lo split for next step
#pragma unroll
    for (int mt = 0; mt < 4; mt++) {
        const int r = row0 + wm * 64 + mt * 16 + (lane >> 2);
#pragma unroll
        for (int nt = 0; nt < 4; nt++) {
            const int c = col0 + wn * 32 + nt * 8 + (lane & 3) * 2;
            const size_t o0 = (size_t)r * N + c;
            const size_t o1 = o0 + (size_t)8 * N;
            const float2 c0 = *(const float2*)(Cold + o0);
            const float2 c1 = *(const float2*)(Cold + o1);
            const float v0 = acc[mt][nt][0] - c0.x;
            const float v1 = acc[mt][nt][1] - c0.y;
            const float v2 = acc[mt][nt][2] - c1.x;
            const float v3 = acc[mt][nt][3] - c1.y;
            *(float2*)(Tout + o0) = make_float2(v0, v1);
            *(float2*)(Tout + o1) = make_float2(v2, v3);
            const __nv_bfloat16 h0 = __float2bfloat16(v0), h1 = __float2bfloat16(v1);
            const __nv_bfloat16 h2 = __float2bfloat16(v2), h3 = __float2bfloat16(v3);
            *(__nv_bfloat162*)(HiOut + o0) = __halves2bfloat162(h0, h1);
            *(__nv_bfloat162*)(HiOut + o1) = __halves2bfloat162(h2, h3);
            *(__nv_bfloat162*)(LoOut + o0) = __halves2bfloat162(
                __float2bfloat16(v0 - __bfloat162float(h0)),
                __float2bfloat16(v1 - __bfloat162float(h1)));
            *(__nv_bfloat162*)(LoOut + o1) = __halves2bfloat162(
                __float2bfloat16(v2 - __bfloat162float(h2)),
                __float2bfloat16(v3 - __bfloat162float(h3)));
        }
    }
}

// ---------------------------------------------------------------------------
// Finalize: out[f*N+i][j] = sum_k cw[k][f] * T_k[i][j]
// ---------------------------------------------------------------------------
__global__ void __launch_bounds__(256)
cheb_finalize(const float* __restrict__ Ts, const float* __restrict__ cw,
              float* __restrict__ out) {
    __shared__ float cws[NCOEF * NF];
    if (threadIdx.x < NCOEF * NF) cws[threadIdx.x] = cw[threadIdx.x];
    __syncthreads();

    size_t idx = (size_t)blockIdx.x * 256 + threadIdx.x;
    int i = (int)(idx >> 9);
    int j = ((int)(idx & 511)) << 2;
    size_t off = (size_t)i * N + j;

    float4 t[NCOEF];
#pragma unroll
    for (int k = 0; k < NCOEF; k++)
        t[k] = *(const float4*)(Ts + (size_t)k * NN + off);

#pragma unroll
    for (int f = 0; f < NF; f++) {
        float4 s = make_float4(0.f, 0.f, 0.f, 0.f);
#pragma unroll
        for (int k = 0; k < NCOEF; k++) {
            float c = cws[k * NF + f];
            s.x += c * t[k].x; s.y += c * t[k].y;
            s.z += c * t[k].z; s.w += c * t[k].w;
        }
        *(float4*)(out + (size_t)f * NN + off) = s;
    }
}

// ---------------------------------------------------------------------------
// Launch (graph-capturable, allocation-free)
// ---------------------------------------------------------------------------
extern "C" void kernel_launch(void* const* d_in, const int* in_sizes, int n_in,
                              void* d_out, int out_size) {
    const float* L    = (const float*)d_in[0];
    const float* taus = (const float*)d_in[1];
    float* out = (float*)d_out;

    float *Ts, *cw;
    __nv_bfloat16 *hi, *lo, *Fhi;
    cudaGetSymbolAddress((void**)&Ts, g_Ts);
    cudaGetSymbolAddress((void**)&cw, g_cw);
    cudaGetSymbolAddress((void**)&hi, g_hi);
    cudaGetSymbolAddress((void**)&lo, g_lo);
    cudaGetSymbolAddress((void**)&Fhi, g_Fhi);

    cudaFuncSetAttribute(cheb_hmma, cudaFuncAttributeMaxDynamicSharedMemorySize,
                         SMEM_GEMM);

    cheb_coeff<<<1, 160>>>(taus, cw);
    cheb_prep<<<(int)(NN / 4 / 256), 256>>>(L, Ts, Ts + NN, hi + NN, lo + NN, Fhi);

    dim3 grid(N / 128, N / 128), block(256);
    for (int k = 2; k <= ORDER; k++) {
        cheb_hmma<<<grid, block, SMEM_GEMM>>>(
            Fhi,
            hi + (size_t)(k - 1) * NN, lo + (size_t)(k - 1) * NN,   // B = T_{k-1}
            Ts + (size_t)(k - 2) * NN,                              // Cold = T_{k-2}
            Ts + (size_t)k * NN,                                    // T_k fp32
            hi + (size_t)k * NN, lo + (size_t)k * NN);              // T_k split
    }
    cheb_finalize<<<(int)(NN / 4 / 256), 256>>>(Ts, cw, out);
}